// round 1
// baseline (speedup 1.0000x reference)
#include <cuda_runtime.h>
#include <cstdint>

#define N_NODES 50000
#define N_EDGES 800000
#define N_E2    850000      // edges + self loops
#define IN_DIM  128
#define HID     64
#define HEADS   4
#define HC      256         // HEADS*HID
#define NEG_SLOPE 0.2f

// ---------------- scratch (device globals; no runtime alloc) ----------------
__device__ float    g_xl1[N_NODES * HC];
__device__ float    g_xr1[N_NODES * HC];
__device__ float    g_out1[N_NODES * HC];
__device__ float    g_logits1[N_E2 * 4];     // reused as exp values in pass B
__device__ unsigned g_mx1[N_NODES * 4];      // encoded float max
__device__ float    g_denom1[N_NODES * 4];
__device__ float    g_hl2[N_NODES];
__device__ float    g_hr2[N_NODES];
__device__ float    g_logits2[N_E2];
__device__ unsigned g_mx2[N_NODES];
__device__ float    g_denom2[N_NODES];
__device__ float    g_out2[N_NODES];
__device__ float    g_attr_sum[3];
__device__ unsigned g_smax;
__device__ float    g_ssum;

// ---------------- helpers ----------------
__device__ __forceinline__ unsigned encf(float f) {
    unsigned u = __float_as_uint(f);
    return (u & 0x80000000u) ? ~u : (u | 0x80000000u);
}
__device__ __forceinline__ float decf(unsigned u) {
    return (u & 0x80000000u) ? __uint_as_float(u & 0x7FFFFFFFu)
                             : __uint_as_float(~u);
}
__device__ __forceinline__ void red4(float* p, float4 v) {
    asm volatile("red.global.add.v4.f32 [%0], {%1,%2,%3,%4};"
                 :: "l"(p), "f"(v.x), "f"(v.y), "f"(v.z), "f"(v.w) : "memory");
}
__device__ __forceinline__ float warp_sum(float v) {
    #pragma unroll
    for (int o = 16; o; o >>= 1) v += __shfl_down_sync(0xffffffffu, v, o);
    return v;
}

// ---------------- init ----------------
__global__ void k_zero_out1() {
    int n4 = N_NODES * HC / 4;
    float4 z = make_float4(0.f, 0.f, 0.f, 0.f);
    for (int i = blockIdx.x * blockDim.x + threadIdx.x; i < n4;
         i += gridDim.x * blockDim.x)
        reinterpret_cast<float4*>(g_out1)[i] = z;
}

__global__ void k_zero_small() {
    for (int i = blockIdx.x * blockDim.x + threadIdx.x; i <= 550000;
         i += gridDim.x * blockDim.x) {
        if      (i < 200000) { g_mx1[i] = 0u; }
        else if (i < 400000) { g_denom1[i - 200000] = 0.f; }
        else if (i < 450000) { g_mx2[i - 400000] = 0u; }
        else if (i < 500000) { g_denom2[i - 450000] = 0.f; }
        else if (i < 550000) { g_out2[i - 500000] = 0.f; }
        else { g_attr_sum[0] = 0.f; g_attr_sum[1] = 0.f; g_attr_sum[2] = 0.f;
               g_smax = 0u; g_ssum = 0.f; }
    }
}

// mean of edge_attr columns (for self-loop fill)
__global__ void k_attr_mean(const float* __restrict__ ea) {
    float s0 = 0.f, s1 = 0.f, s2 = 0.f;
    for (int e = blockIdx.x * blockDim.x + threadIdx.x; e < N_EDGES;
         e += gridDim.x * blockDim.x) {
        s0 += ea[e * 3 + 0]; s1 += ea[e * 3 + 1]; s2 += ea[e * 3 + 2];
    }
    s0 = warp_sum(s0); s1 = warp_sum(s1); s2 = warp_sum(s2);
    if ((threadIdx.x & 31) == 0) {
        atomicAdd(&g_attr_sum[0], s0);
        atomicAdd(&g_attr_sum[1], s1);
        atomicAdd(&g_attr_sum[2], s2);
    }
}

// ---------------- SGEMM: C[N,256] = A[N,128] @ B[128,256] ----------------
// BM=64 BN=64 BK=16, 256 threads, 4x4 register tile per thread.
__global__ void k_sgemm(const float* __restrict__ A, const float* __restrict__ B,
                        int which /*0 -> g_xl1, 1 -> g_xr1*/) {
    __shared__ float As[16][65];
    __shared__ float Bs[16][64];
    const int K = IN_DIM, M = HC;
    int bx = blockIdx.x;                // 0..3 (col tiles)
    int by = blockIdx.y;                // row tiles
    int tid = threadIdx.x;
    int tr = tid / 16, tc = tid % 16;
    int row0 = by * 64, col0 = bx * 64;
    float acc[4][4] = {};
    for (int k0 = 0; k0 < K; k0 += 16) {
        #pragma unroll
        for (int i = tid; i < 1024; i += 256) {
            int kk = i % 16, m = i / 16;
            int r = row0 + m;
            As[kk][m] = (r < N_NODES) ? A[r * K + k0 + kk] : 0.f;
        }
        #pragma unroll
        for (int i = tid; i < 1024; i += 256) {
            int n = i % 64, kk = i / 64;
            Bs[kk][n] = B[(k0 + kk) * M + col0 + n];
        }
        __syncthreads();
        #pragma unroll
        for (int kk = 0; kk < 16; kk++) {
            float a[4], b[4];
            #pragma unroll
            for (int u = 0; u < 4; u++) a[u] = As[kk][tr * 4 + u];
            float4 b4 = *reinterpret_cast<const float4*>(&Bs[kk][tc * 4]);
            b[0] = b4.x; b[1] = b4.y; b[2] = b4.z; b[3] = b4.w;
            #pragma unroll
            for (int u = 0; u < 4; u++)
                #pragma unroll
                for (int v = 0; v < 4; v++)
                    acc[u][v] += a[u] * b[v];
        }
        __syncthreads();
    }
    float* C = which ? g_xr1 : g_xl1;
    #pragma unroll
    for (int u = 0; u < 4; u++) {
        int r = row0 + tr * 4 + u;
        if (r < N_NODES) {
            #pragma unroll
            for (int v = 0; v < 4; v++)
                C[r * M + col0 + tc * 4 + v] = acc[u][v];
        }
    }
}

// ---------------- layer 1, pass A: logits + segment max ----------------
// one warp per edge
__global__ void k_edge_logits1(const int* __restrict__ ei,
                               const float* __restrict__ ea,
                               const float* __restrict__ W1e,
                               const float* __restrict__ att1) {
    __shared__ float sW[768];
    __shared__ float sA[256];
    __shared__ float sMean[3];
    int tid = threadIdx.x;
    for (int i = tid; i < 768; i += 256) sW[i] = W1e[i];
    if (tid < 256) sA[tid] = att1[tid];
    if (tid < 3) sMean[tid] = g_attr_sum[tid] * (1.0f / N_EDGES);
    __syncthreads();

    int e = blockIdx.x * 8 + (tid >> 5);
    int lane = tid & 31;
    if (e >= N_E2) return;
    int src, dst; float a0, a1, a2;
    if (e < N_EDGES) {
        src = ei[e]; dst = ei[N_EDGES + e];
        a0 = ea[e * 3]; a1 = ea[e * 3 + 1]; a2 = ea[e * 3 + 2];
    } else {
        src = dst = e - N_EDGES;
        a0 = sMean[0]; a1 = sMean[1]; a2 = sMean[2];
    }
    const float2* xl = reinterpret_cast<const float2*>(g_xl1 + (size_t)src * HC);
    const float2* xr = reinterpret_cast<const float2*>(g_xr1 + (size_t)dst * HC);
    #pragma unroll
    for (int h = 0; h < 4; h++) {
        int i2 = h * 32 + lane;     // float2 index
        float2 l = xl[i2], r = xr[i2];
        int i = i2 * 2;
        float e0 = a0 * sW[i]     + a1 * sW[256 + i]     + a2 * sW[512 + i];
        float e1 = a0 * sW[i + 1] + a1 * sW[256 + i + 1] + a2 * sW[512 + i + 1];
        float m0 = l.x + r.x + e0; m0 = m0 > 0.f ? m0 : NEG_SLOPE * m0;
        float m1 = l.y + r.y + e1; m1 = m1 > 0.f ? m1 : NEG_SLOPE * m1;
        float p = m0 * sA[i] + m1 * sA[i + 1];
        p = warp_sum(p);
        if (lane == 0) {
            g_logits1[(size_t)e * 4 + h] = p;
            atomicMax(&g_mx1[dst * 4 + h], encf(p));
        }
    }
}

// ---------------- layer 1, pass B: exp + segment sum ----------------
__global__ void k_edge_exp1(const int* __restrict__ ei) {
    int e = blockIdx.x * blockDim.x + threadIdx.x;
    if (e >= N_E2) return;
    int dst = (e < N_EDGES) ? ei[N_EDGES + e] : e - N_EDGES;
    float4 lg = *reinterpret_cast<float4*>(&g_logits1[(size_t)e * 4]);
    float4 a;
    a.x = __expf(lg.x - decf(g_mx1[dst * 4 + 0]));
    a.y = __expf(lg.y - decf(g_mx1[dst * 4 + 1]));
    a.z = __expf(lg.z - decf(g_mx1[dst * 4 + 2]));
    a.w = __expf(lg.w - decf(g_mx1[dst * 4 + 3]));
    *reinterpret_cast<float4*>(&g_logits1[(size_t)e * 4]) = a;
    red4(&g_denom1[dst * 4], a);
}

// ---------------- layer 1, pass C: weighted scatter ----------------
// one warp per edge; each lane does 2 float4 vec reductions
__global__ void k_edge_aggr1(const int* __restrict__ ei) {
    int e = blockIdx.x * 8 + (threadIdx.x >> 5);
    int lane = threadIdx.x & 31;
    if (e >= N_E2) return;
    int src, dst;
    if (e < N_EDGES) { src = ei[e]; dst = ei[N_EDGES + e]; }
    else             { src = dst = e - N_EDGES; }
    float al[4];
    #pragma unroll
    for (int h = 0; h < 4; h++)
        al[h] = g_logits1[(size_t)e * 4 + h] / g_denom1[dst * 4 + h];
    const float4* xl = reinterpret_cast<const float4*>(g_xl1 + (size_t)src * HC);
    float* outp = g_out1 + (size_t)dst * HC;
    float s0 = (lane < 16) ? al[0] : al[1];   // j = lane      -> head 0/1
    float s1 = (lane < 16) ? al[2] : al[3];   // j = lane + 32 -> head 2/3
    float4 v = xl[lane];
    v.x *= s0; v.y *= s0; v.z *= s0; v.w *= s0;
    red4(outp + lane * 4, v);
    float4 w = xl[lane + 32];
    w.x *= s1; w.y *= s1; w.z *= s1; w.w *= s1;
    red4(outp + (lane + 32) * 4, w);
}

// ---------------- layer 2 node transform: h=elu(out1+b1), hl2=h@W2l, hr2=h@W2r
__global__ void k_node_l2(const float* __restrict__ b1,
                          const float* __restrict__ W2l,
                          const float* __restrict__ W2r) {
    int n = blockIdx.x * 8 + (threadIdx.x >> 5);
    int lane = threadIdx.x & 31;
    if (n >= N_NODES) return;
    const float* row = g_out1 + (size_t)n * HC;
    float accL = 0.f, accR = 0.f;
    #pragma unroll
    for (int i = lane; i < HC; i += 32) {
        float v = row[i] + b1[i];
        v = v > 0.f ? v : (__expf(v) - 1.f);   // ELU
        accL += v * W2l[i];
        accR += v * W2r[i];
    }
    accL = warp_sum(accL);
    accR = warp_sum(accR);
    if (lane == 0) { g_hl2[n] = accL; g_hr2[n] = accR; }
}

// ---------------- layer 2 edge passes (scalar) ----------------
__global__ void k_edge_logits2(const int* __restrict__ ei,
                               const float* __restrict__ ea,
                               const float* __restrict__ W2e,
                               const float* __restrict__ att2) {
    __shared__ float sMean[3];
    __shared__ float sW[3];
    __shared__ float sAtt;
    if (threadIdx.x < 3) {
        sMean[threadIdx.x] = g_attr_sum[threadIdx.x] * (1.0f / N_EDGES);
        sW[threadIdx.x] = W2e[threadIdx.x];
    }
    if (threadIdx.x == 0) sAtt = att2[0];
    __syncthreads();
    int e = blockIdx.x * blockDim.x + threadIdx.x;
    if (e >= N_E2) return;
    int src, dst; float a0, a1, a2;
    if (e < N_EDGES) {
        src = ei[e]; dst = ei[N_EDGES + e];
        a0 = ea[e * 3]; a1 = ea[e * 3 + 1]; a2 = ea[e * 3 + 2];
    } else {
        src = dst = e - N_EDGES;
        a0 = sMean[0]; a1 = sMean[1]; a2 = sMean[2];
    }
    float m = g_hl2[src] + g_hr2[dst] + a0 * sW[0] + a1 * sW[1] + a2 * sW[2];
    m = m > 0.f ? m : NEG_SLOPE * m;
    float lg = sAtt * m;
    g_logits2[e] = lg;
    atomicMax(&g_mx2[dst], encf(lg));
}

__global__ void k_edge_exp2(const int* __restrict__ ei) {
    int e = blockIdx.x * blockDim.x + threadIdx.x;
    if (e >= N_E2) return;
    int dst = (e < N_EDGES) ? ei[N_EDGES + e] : e - N_EDGES;
    float a = __expf(g_logits2[e] - decf(g_mx2[dst]));
    g_logits2[e] = a;
    atomicAdd(&g_denom2[dst], a);
}

__global__ void k_edge_aggr2(const int* __restrict__ ei) {
    int e = blockIdx.x * blockDim.x + threadIdx.x;
    if (e >= N_E2) return;
    int src, dst;
    if (e < N_EDGES) { src = ei[e]; dst = ei[N_EDGES + e]; }
    else             { src = dst = e - N_EDGES; }
    float alpha = g_logits2[e] / g_denom2[dst];
    atomicAdd(&g_out2[dst], g_hl2[src] * alpha);
}

// ---------------- final scores + global softmax ----------------
__global__ void k_scores(const float* __restrict__ b2, float* __restrict__ out) {
    int n = blockIdx.x * blockDim.x + threadIdx.x;
    if (n >= N_NODES) return;
    float s = g_out2[n] + b2[0];
    g_out2[n] = s;
    out[N_NODES + n] = s;
}

__global__ void k_smax() {
    float m = -3.0e38f;
    for (int n = blockIdx.x * blockDim.x + threadIdx.x; n < N_NODES;
         n += gridDim.x * blockDim.x)
        m = fmaxf(m, g_out2[n]);
    #pragma unroll
    for (int o = 16; o; o >>= 1)
        m = fmaxf(m, __shfl_down_sync(0xffffffffu, m, o));
    if ((threadIdx.x & 31) == 0) atomicMax(&g_smax, encf(m));
}

__global__ void k_ssum() {
    float mx = decf(g_smax);
    float s = 0.f;
    for (int n = blockIdx.x * blockDim.x + threadIdx.x; n < N_NODES;
         n += gridDim.x * blockDim.x)
        s += __expf(g_out2[n] - mx);
    s = warp_sum(s);
    if ((threadIdx.x & 31) == 0) atomicAdd(&g_ssum, s);
}

__global__ void k_weights(float* __restrict__ out) {
    float mx = decf(g_smax);
    float inv = 1.0f / g_ssum;
    int n = blockIdx.x * blockDim.x + threadIdx.x;
    if (n >= N_NODES) return;
    out[n] = __expf(g_out2[n] - mx) * inv;
}

// ---------------- launch ----------------
extern "C" void kernel_launch(void* const* d_in, const int* in_sizes, int n_in,
                              void* d_out, int out_size) {
    const float* x    = (const float*)d_in[0];
    const float* ea   = (const float*)d_in[1];
    const float* W1l  = (const float*)d_in[2];
    const float* W1r  = (const float*)d_in[3];
    const float* W1e  = (const float*)d_in[4];
    const float* att1 = (const float*)d_in[5];
    const float* b1   = (const float*)d_in[6];
    const float* W2l  = (const float*)d_in[7];
    const float* W2r  = (const float*)d_in[8];
    const float* W2e  = (const float*)d_in[9];
    const float* att2 = (const float*)d_in[10];
    const float* b2   = (const float*)d_in[11];
    const int*   ei   = (const int*)d_in[12];
    float* out = (float*)d_out;

    // init
    k_zero_out1<<<2048, 256>>>();
    k_zero_small<<<2150, 256>>>();
    k_attr_mean<<<256, 256>>>(ea);

    // dense transforms
    dim3 gg(4, (N_NODES + 63) / 64);
    k_sgemm<<<gg, 256>>>(x, W1l, 0);
    k_sgemm<<<gg, 256>>>(x, W1r, 1);

    // layer 1 edge passes
    int ewarp_blocks = (N_E2 + 7) / 8;
    int ethr_blocks  = (N_E2 + 255) / 256;
    k_edge_logits1<<<ewarp_blocks, 256>>>(ei, ea, W1e, att1);
    k_edge_exp1<<<ethr_blocks, 256>>>(ei);
    k_edge_aggr1<<<ewarp_blocks, 256>>>(ei);

    // layer 2
    k_node_l2<<<(N_NODES + 7) / 8, 256>>>(b1, W2l, W2r);
    k_edge_logits2<<<ethr_blocks, 256>>>(ei, ea, W2e, att2);
    k_edge_exp2<<<ethr_blocks, 256>>>(ei);
    k_edge_aggr2<<<ethr_blocks, 256>>>(ei);

    // scores + global softmax
    int nthr_blocks = (N_NODES + 255) / 256;
    k_scores<<<nthr_blocks, 256>>>(b2, out);
    k_smax<<<128, 256>>>();
    k_ssum<<<128, 256>>>();
    k_weights<<<nthr_blocks, 256>>>(out);
}

// round 3
// speedup vs baseline: 1.2270x; 1.2270x over previous
#include <cuda_runtime.h>
#include <cstdint>

#define N_NODES 50000
#define N_EDGES 800000
#define N_E2    850000      // edges + self loops
#define IN_DIM  128
#define HID     64
#define HEADS   4
#define HC      256         // HEADS*HID
#define NEG_SLOPE 0.2f

// ---------------- scratch (device globals; no runtime alloc) ----------------
__device__ float    g_xl1[N_NODES * HC];
__device__ float    g_xr1[N_NODES * HC];
__device__ float    g_out1[N_NODES * HC];
__device__ float    g_exp1[N_E2 * 4];        // exp(logit) per edge per head
__device__ float    g_denom1[N_NODES * 4];
__device__ float    g_hl2[N_NODES];
__device__ float    g_hr2[N_NODES];
__device__ float    g_exp2[N_E2];
__device__ float    g_denom2[N_NODES];
__device__ float    g_out2[N_NODES];
__device__ float    g_attr_sum[3];
__device__ unsigned g_smax;
__device__ float    g_ssum;

// ---------------- helpers ----------------
__device__ __forceinline__ unsigned encf(float f) {
    unsigned u = __float_as_uint(f);
    return (u & 0x80000000u) ? ~u : (u | 0x80000000u);
}
__device__ __forceinline__ float decf(unsigned u) {
    return (u & 0x80000000u) ? __uint_as_float(u & 0x7FFFFFFFu)
                             : __uint_as_float(~u);
}
__device__ __forceinline__ void red4(float* p, float4 v) {
    asm volatile("red.global.add.v4.f32 [%0], {%1,%2,%3,%4};"
                 :: "l"(p), "f"(v.x), "f"(v.y), "f"(v.z), "f"(v.w) : "memory");
}
__device__ __forceinline__ float warp_sum(float v) {
    #pragma unroll
    for (int o = 16; o; o >>= 1) v += __shfl_down_sync(0xffffffffu, v, o);
    return v;
}

// ---------------- init: zero everything that gets atomically accumulated ----
__global__ void k_zero() {
    int tid = blockIdx.x * blockDim.x + threadIdx.x;
    int stride = gridDim.x * blockDim.x;
    float4 z = make_float4(0.f, 0.f, 0.f, 0.f);
    int n4 = N_NODES * HC / 4;
    for (int i = tid; i < n4; i += stride)
        reinterpret_cast<float4*>(g_out1)[i] = z;
    for (int i = tid; i < N_NODES * 4; i += stride) g_denom1[i] = 0.f;
    for (int i = tid; i < N_NODES; i += stride) { g_denom2[i] = 0.f; g_out2[i] = 0.f; }
    if (tid == 0) {
        g_attr_sum[0] = 0.f; g_attr_sum[1] = 0.f; g_attr_sum[2] = 0.f;
        g_smax = 0u; g_ssum = 0.f;
    }
}

// mean of edge_attr columns (for self-loop fill)
__global__ void k_attr_mean(const float* __restrict__ ea) {
    float s0 = 0.f, s1 = 0.f, s2 = 0.f;
    for (int e = blockIdx.x * blockDim.x + threadIdx.x; e < N_EDGES;
         e += gridDim.x * blockDim.x) {
        s0 += ea[e * 3 + 0]; s1 += ea[e * 3 + 1]; s2 += ea[e * 3 + 2];
    }
    s0 = warp_sum(s0); s1 = warp_sum(s1); s2 = warp_sum(s2);
    if ((threadIdx.x & 31) == 0) {
        atomicAdd(&g_attr_sum[0], s0);
        atomicAdd(&g_attr_sum[1], s1);
        atomicAdd(&g_attr_sum[2], s2);
    }
}

// ---------------- SGEMM: C[N,256] = A[N,128] @ B[128,256] ----------------
// BM=128 BN=64 BK=16, 256 threads, 8x4 register tile per thread.
__global__ __launch_bounds__(256) void k_sgemm(const float* __restrict__ A,
                                               const float* __restrict__ B,
                                               int which /*0->g_xl1, 1->g_xr1*/) {
    __shared__ float As[16][132];   // [k][m], padded
    __shared__ float Bs[16][64];    // [k][n]
    const int K = IN_DIM, M = HC;
    int row0 = blockIdx.y * 128, col0 = blockIdx.x * 64;
    int tid = threadIdx.x;
    int tr = tid >> 4, tc = tid & 15;    // tr:0..15 (8 rows each), tc:0..15 (4 cols each)
    float acc[8][4] = {};
    for (int k0 = 0; k0 < K; k0 += 16) {
        // load A tile: 128 rows x 16 k = 512 float4 (transpose into As[k][m])
        #pragma unroll
        for (int i = tid; i < 512; i += 256) {
            int m = i >> 2, kq = (i & 3) * 4;
            int r = row0 + m;
            float4 v = (r < N_NODES)
                ? *reinterpret_cast<const float4*>(&A[(size_t)r * K + k0 + kq])
                : make_float4(0.f, 0.f, 0.f, 0.f);
            As[kq + 0][m] = v.x; As[kq + 1][m] = v.y;
            As[kq + 2][m] = v.z; As[kq + 3][m] = v.w;
        }
        // load B tile: 16 k x 64 n = 256 float4
        {
            int kk = tid >> 4, nq = (tid & 15) * 4;
            *reinterpret_cast<float4*>(&Bs[kk][nq]) =
                *reinterpret_cast<const float4*>(&B[(size_t)(k0 + kk) * M + col0 + nq]);
        }
        __syncthreads();
        #pragma unroll
        for (int kk = 0; kk < 16; kk++) {
            float4 a0 = *reinterpret_cast<const float4*>(&As[kk][tr * 8]);
            float4 a1 = *reinterpret_cast<const float4*>(&As[kk][tr * 8 + 4]);
            float4 b4 = *reinterpret_cast<const float4*>(&Bs[kk][tc * 4]);
            float a[8] = {a0.x, a0.y, a0.z, a0.w, a1.x, a1.y, a1.z, a1.w};
            float b[4] = {b4.x, b4.y, b4.z, b4.w};
            #pragma unroll
            for (int u = 0; u < 8; u++)
                #pragma unroll
                for (int v = 0; v < 4; v++)
                    acc[u][v] += a[u] * b[v];
        }
        __syncthreads();
    }
    float* C = which ? g_xr1 : g_xl1;
    #pragma unroll
    for (int u = 0; u < 8; u++) {
        int r = row0 + tr * 8 + u;
        if (r < N_NODES)
            *reinterpret_cast<float4*>(&C[(size_t)r * M + col0 + tc * 4]) =
                make_float4(acc[u][0], acc[u][1], acc[u][2], acc[u][3]);
    }
}

// ---------------- layer 1, pass A: logits -> exp -> denom (no segment max) --
// one warp per edge; alpha shift-invariance makes max subtraction unnecessary.
__global__ void k_edge1(const int* __restrict__ ei,
                        const float* __restrict__ ea,
                        const float* __restrict__ W1e,
                        const float* __restrict__ att1) {
    __shared__ float sW[768];
    __shared__ float sA[256];
    __shared__ float sMean[3];
    int tid = threadIdx.x;
    for (int i = tid; i < 768; i += 256) sW[i] = W1e[i];
    if (tid < 256) sA[tid] = att1[tid];
    if (tid < 3) sMean[tid] = g_attr_sum[tid] * (1.0f / N_EDGES);
    __syncthreads();

    int e = blockIdx.x * 8 + (tid >> 5);
    int lane = tid & 31;
    if (e >= N_E2) return;
    int src, dst; float a0, a1, a2;
    if (e < N_EDGES) {
        src = ei[e]; dst = ei[N_EDGES + e];
        a0 = ea[e * 3]; a1 = ea[e * 3 + 1]; a2 = ea[e * 3 + 2];
    } else {
        src = dst = e - N_EDGES;
        a0 = sMean[0]; a1 = sMean[1]; a2 = sMean[2];
    }
    const float2* xl = reinterpret_cast<const float2*>(g_xl1 + (size_t)src * HC);
    const float2* xr = reinterpret_cast<const float2*>(g_xr1 + (size_t)dst * HC);
    float ex[4];
    #pragma unroll
    for (int h = 0; h < 4; h++) {
        int i2 = h * 32 + lane;     // float2 index
        float2 l = xl[i2], r = xr[i2];
        int i = i2 * 2;
        float e0 = a0 * sW[i]     + a1 * sW[256 + i]     + a2 * sW[512 + i];
        float e1 = a0 * sW[i + 1] + a1 * sW[256 + i + 1] + a2 * sW[512 + i + 1];
        float m0 = l.x + r.x + e0; m0 = m0 > 0.f ? m0 : NEG_SLOPE * m0;
        float m1 = l.y + r.y + e1; m1 = m1 > 0.f ? m1 : NEG_SLOPE * m1;
        float p = m0 * sA[i] + m1 * sA[i + 1];
        p = warp_sum(p);
        if (lane == 0) ex[h] = __expf(p);
    }
    if (lane == 0) {
        float4 v = make_float4(ex[0], ex[1], ex[2], ex[3]);
        *reinterpret_cast<float4*>(&g_exp1[(size_t)e * 4]) = v;
        red4(&g_denom1[dst * 4], v);
    }
}

// ---------------- layer 1, pass B: weighted scatter ----------------
// one warp per edge; each lane does 2 float4 vec reductions
__global__ void k_edge_aggr1(const int* __restrict__ ei) {
    int e = blockIdx.x * 8 + (threadIdx.x >> 5);
    int lane = threadIdx.x & 31;
    if (e >= N_E2) return;
    int src, dst;
    if (e < N_EDGES) { src = ei[e]; dst = ei[N_EDGES + e]; }
    else             { src = dst = e - N_EDGES; }
    float al[4];
    #pragma unroll
    for (int h = 0; h < 4; h++)
        al[h] = g_exp1[(size_t)e * 4 + h] / g_denom1[dst * 4 + h];
    const float4* xl = reinterpret_cast<const float4*>(g_xl1 + (size_t)src * HC);
    float* outp = g_out1 + (size_t)dst * HC;
    float s0 = (lane < 16) ? al[0] : al[1];   // j = lane      -> head 0/1
    float s1 = (lane < 16) ? al[2] : al[3];   // j = lane + 32 -> head 2/3
    float4 v = xl[lane];
    v.x *= s0; v.y *= s0; v.z *= s0; v.w *= s0;
    red4(outp + lane * 4, v);
    float4 w = xl[lane + 32];
    w.x *= s1; w.y *= s1; w.z *= s1; w.w *= s1;
    red4(outp + (lane + 32) * 4, w);
}

// ---------------- layer 2 node transform: h=elu(out1+b1), hl2=h@W2l, hr2=h@W2r
__global__ void k_node_l2(const float* __restrict__ b1,
                          const float* __restrict__ W2l,
                          const float* __restrict__ W2r) {
    int n = blockIdx.x * 8 + (threadIdx.x >> 5);
    int lane = threadIdx.x & 31;
    if (n >= N_NODES) return;
    const float* row = g_out1 + (size_t)n * HC;
    float accL = 0.f, accR = 0.f;
    #pragma unroll
    for (int i = lane; i < HC; i += 32) {
        float v = row[i] + b1[i];
        v = v > 0.f ? v : (__expf(v) - 1.f);   // ELU
        accL += v * W2l[i];
        accR += v * W2r[i];
    }
    accL = warp_sum(accL);
    accR = warp_sum(accR);
    if (lane == 0) { g_hl2[n] = accL; g_hr2[n] = accR; }
}

// ---------------- layer 2 edge pass A: logits -> exp -> denom ----------------
__global__ void k_edge2(const int* __restrict__ ei,
                        const float* __restrict__ ea,
                        const float* __restrict__ W2e,
                        const float* __restrict__ att2) {
    __shared__ float sMean[3];
    __shared__ float sW[3];
    __shared__ float sAtt;
    if (threadIdx.x < 3) {
        sMean[threadIdx.x] = g_attr_sum[threadIdx.x] * (1.0f / N_EDGES);
        sW[threadIdx.x] = W2e[threadIdx.x];
    }
    if (threadIdx.x == 0) sAtt = att2[0];
    __syncthreads();
    int e = blockIdx.x * blockDim.x + threadIdx.x;
    if (e >= N_E2) return;
    int src, dst; float a0, a1, a2;
    if (e < N_EDGES) {
        src = ei[e]; dst = ei[N_EDGES + e];
        a0 = ea[e * 3]; a1 = ea[e * 3 + 1]; a2 = ea[e * 3 + 2];
    } else {
        src = dst = e - N_EDGES;
        a0 = sMean[0]; a1 = sMean[1]; a2 = sMean[2];
    }
    float m = g_hl2[src] + g_hr2[dst] + a0 * sW[0] + a1 * sW[1] + a2 * sW[2];
    m = m > 0.f ? m : NEG_SLOPE * m;
    float a = __expf(sAtt * m);
    g_exp2[e] = a;
    atomicAdd(&g_denom2[dst], a);
}

// ---------------- layer 2 pass B: weighted scatter ----------------
__global__ void k_edge_aggr2(const int* __restrict__ ei) {
    int e = blockIdx.x * blockDim.x + threadIdx.x;
    if (e >= N_E2) return;
    int src, dst;
    if (e < N_EDGES) { src = ei[e]; dst = ei[N_EDGES + e]; }
    else             { src = dst = e - N_EDGES; }
    float alpha = g_exp2[e] / g_denom2[dst];
    atomicAdd(&g_out2[dst], g_hl2[src] * alpha);
}

// ---------------- final scores + global softmax ----------------
__global__ void k_scores(const float* __restrict__ b2, float* __restrict__ out) {
    int n = blockIdx.x * blockDim.x + threadIdx.x;
    if (n >= N_NODES) return;
    float s = g_out2[n] + b2[0];
    g_out2[n] = s;
    out[N_NODES + n] = s;
}

__global__ void k_smax() {
    float m = -3.0e38f;
    for (int n = blockIdx.x * blockDim.x + threadIdx.x; n < N_NODES;
         n += gridDim.x * blockDim.x)
        m = fmaxf(m, g_out2[n]);
    #pragma unroll
    for (int o = 16; o; o >>= 1)
        m = fmaxf(m, __shfl_down_sync(0xffffffffu, m, o));
    if ((threadIdx.x & 31) == 0) atomicMax(&g_smax, encf(m));
}

__global__ void k_ssum() {
    float mx = decf(g_smax);
    float s = 0.f;
    for (int n = blockIdx.x * blockDim.x + threadIdx.x; n < N_NODES;
         n += gridDim.x * blockDim.x)
        s += __expf(g_out2[n] - mx);
    s = warp_sum(s);
    if ((threadIdx.x & 31) == 0) atomicAdd(&g_ssum, s);
}

__global__ void k_weights(float* __restrict__ out) {
    float mx = decf(g_smax);
    float inv = 1.0f / g_ssum;
    int n = blockIdx.x * blockDim.x + threadIdx.x;
    if (n >= N_NODES) return;
    out[n] = __expf(g_out2[n] - mx) * inv;
}

// ---------------- launch ----------------
extern "C" void kernel_launch(void* const* d_in, const int* in_sizes, int n_in,
                              void* d_out, int out_size) {
    const float* x    = (const float*)d_in[0];
    const float* ea   = (const float*)d_in[1];
    const float* W1l  = (const float*)d_in[2];
    const float* W1r  = (const float*)d_in[3];
    const float* W1e  = (const float*)d_in[4];
    const float* att1 = (const float*)d_in[5];
    const float* b1   = (const float*)d_in[6];
    const float* W2l  = (const float*)d_in[7];
    const float* W2r  = (const float*)d_in[8];
    const float* W2e  = (const float*)d_in[9];
    const float* att2 = (const float*)d_in[10];
    const float* b2   = (const float*)d_in[11];
    const int*   ei   = (const int*)d_in[12];
    float* out = (float*)d_out;

    // init
    k_zero<<<2048, 256>>>();
    k_attr_mean<<<256, 256>>>(ea);

    // dense transforms (128x64 tiles)
    dim3 gg(4, (N_NODES + 127) / 128);
    k_sgemm<<<gg, 256>>>(x, W1l, 0);
    k_sgemm<<<gg, 256>>>(x, W1r, 1);

    // layer 1 edge passes
    int ewarp_blocks = (N_E2 + 7) / 8;
    int ethr_blocks  = (N_E2 + 255) / 256;
    k_edge1<<<ewarp_blocks, 256>>>(ei, ea, W1e, att1);
    k_edge_aggr1<<<ewarp_blocks, 256>>>(ei);

    // layer 2
    k_node_l2<<<(N_NODES + 7) / 8, 256>>>(b1, W2l, W2r);
    k_edge2<<<ethr_blocks, 256>>>(ei, ea, W2e, att2);
    k_edge_aggr2<<<ethr_blocks, 256>>>(ei);

    // scores + global softmax
    int nthr_blocks = (N_NODES + 255) / 256;
    k_scores<<<nthr_blocks, 256>>>(b2, out);
    k_smax<<<128, 256>>>();
    k_ssum<<<128, 256>>>();
    k_weights<<<nthr_blocks, 256>>>(out);
}

// round 4
// speedup vs baseline: 1.6329x; 1.3308x over previous
#include <cuda_runtime.h>
#include <cstdint>

#define N_NODES 50000
#define N_EDGES 800000
#define N_E2    850000      // edges + self loops
#define IN_DIM  128
#define HID     64
#define HEADS   4
#define HC      256         // HEADS*HID
#define NEG_SLOPE 0.2f

// ---------------- scratch (device globals; no runtime alloc) ----------------
__device__ float    g_xl1[N_NODES * HC];
__device__ float    g_xr1[N_NODES * HC];
__device__ int      g_deg[N_NODES];
__device__ int      g_start[N_NODES];
__device__ int      g_cursor[N_NODES];
__device__ int      g_csr_src[N_E2];
__device__ int      g_csr_eid[N_E2];
__device__ float    g_hl2[N_NODES];
__device__ float    g_hr2[N_NODES];
__device__ float    g_out2[N_NODES];
__device__ float    g_attr_sum[3];
__device__ unsigned g_smax;
__device__ float    g_ssum;

// ---------------- helpers ----------------
__device__ __forceinline__ unsigned encf(float f) {
    unsigned u = __float_as_uint(f);
    return (u & 0x80000000u) ? ~u : (u | 0x80000000u);
}
__device__ __forceinline__ float decf(unsigned u) {
    return (u & 0x80000000u) ? __uint_as_float(u & 0x7FFFFFFFu)
                             : __uint_as_float(~u);
}
__device__ __forceinline__ float warp_sum(float v) {
    #pragma unroll
    for (int o = 16; o; o >>= 1) v += __shfl_down_sync(0xffffffffu, v, o);
    return v;
}
__device__ __forceinline__ float warp_sum_all(float v) {   // butterfly: all lanes get result
    #pragma unroll
    for (int o = 16; o; o >>= 1) v += __shfl_xor_sync(0xffffffffu, v, o);
    return v;
}

// ---------------- init ----------------
__global__ void k_zero() {
    int tid = blockIdx.x * blockDim.x + threadIdx.x;
    int stride = gridDim.x * blockDim.x;
    for (int i = tid; i < N_NODES; i += stride) {
        g_deg[i] = 0; g_hl2[i] = 0.f; g_hr2[i] = 0.f;
    }
    if (tid == 0) {
        g_attr_sum[0] = 0.f; g_attr_sum[1] = 0.f; g_attr_sum[2] = 0.f;
        g_smax = 0u; g_ssum = 0.f;
    }
}

// mean of edge_attr columns (for self-loop fill)
__global__ void k_attr_mean(const float* __restrict__ ea) {
    float s0 = 0.f, s1 = 0.f, s2 = 0.f;
    for (int e = blockIdx.x * blockDim.x + threadIdx.x; e < N_EDGES;
         e += gridDim.x * blockDim.x) {
        s0 += ea[e * 3 + 0]; s1 += ea[e * 3 + 1]; s2 += ea[e * 3 + 2];
    }
    s0 = warp_sum(s0); s1 = warp_sum(s1); s2 = warp_sum(s2);
    if ((threadIdx.x & 31) == 0) {
        atomicAdd(&g_attr_sum[0], s0);
        atomicAdd(&g_attr_sum[1], s1);
        atomicAdd(&g_attr_sum[2], s2);
    }
}

// ---------------- CSR build ----------------
__global__ void k_count(const int* __restrict__ ei) {
    int e = blockIdx.x * blockDim.x + threadIdx.x;
    if (e >= N_E2) return;
    int dst = (e < N_EDGES) ? ei[N_EDGES + e] : e - N_EDGES;
    atomicAdd(&g_deg[dst], 1);
}

// single-block exclusive scan (1024 threads, warp-shuffle based)
__global__ void k_scan() {
    __shared__ int warpTot[32];
    __shared__ int sCarry;
    int tid = threadIdx.x, lane = tid & 31, wid = tid >> 5;
    if (tid == 0) sCarry = 0;
    __syncthreads();
    for (int base = 0; base < N_NODES; base += 1024) {
        int i = base + tid;
        int v = (i < N_NODES) ? g_deg[i] : 0;
        int x = v;
        #pragma unroll
        for (int o = 1; o < 32; o <<= 1) {
            int t = __shfl_up_sync(0xffffffffu, x, o);
            if (lane >= o) x += t;
        }
        if (lane == 31) warpTot[wid] = x;
        __syncthreads();
        if (wid == 0) {
            int w = warpTot[lane];
            #pragma unroll
            for (int o = 1; o < 32; o <<= 1) {
                int t = __shfl_up_sync(0xffffffffu, w, o);
                if (lane >= o) w += t;
            }
            warpTot[lane] = w;
        }
        __syncthreads();
        int carry = sCarry;
        int excl = x - v + (wid ? warpTot[wid - 1] : 0) + carry;
        if (i < N_NODES) { g_start[i] = excl; g_cursor[i] = excl; }
        __syncthreads();
        if (tid == 0) sCarry = carry + warpTot[31];
        __syncthreads();
    }
}

__global__ void k_place(const int* __restrict__ ei) {
    int e = blockIdx.x * blockDim.x + threadIdx.x;
    if (e >= N_E2) return;
    int src, dst;
    if (e < N_EDGES) { src = ei[e]; dst = ei[N_EDGES + e]; }
    else             { src = dst = e - N_EDGES; }
    int slot = atomicAdd(&g_cursor[dst], 1);
    g_csr_src[slot] = src;
    g_csr_eid[slot] = e;
}

// ---------------- SGEMM: C[N,256] = A[N,128] @ B[128,256] ----------------
// BM=128 BN=64 BK=16, 256 threads, 8x4 register tile per thread.
__global__ __launch_bounds__(256) void k_sgemm(const float* __restrict__ A,
                                               const float* __restrict__ B,
                                               int which /*0->g_xl1, 1->g_xr1*/) {
    __shared__ float As[16][132];
    __shared__ float Bs[16][64];
    const int K = IN_DIM, M = HC;
    int row0 = blockIdx.y * 128, col0 = blockIdx.x * 64;
    int tid = threadIdx.x;
    int tr = tid >> 4, tc = tid & 15;
    float acc[8][4] = {};
    for (int k0 = 0; k0 < K; k0 += 16) {
        #pragma unroll
        for (int i = tid; i < 512; i += 256) {
            int m = i >> 2, kq = (i & 3) * 4;
            int r = row0 + m;
            float4 v = (r < N_NODES)
                ? *reinterpret_cast<const float4*>(&A[(size_t)r * K + k0 + kq])
                : make_float4(0.f, 0.f, 0.f, 0.f);
            As[kq + 0][m] = v.x; As[kq + 1][m] = v.y;
            As[kq + 2][m] = v.z; As[kq + 3][m] = v.w;
        }
        {
            int kk = tid >> 4, nq = (tid & 15) * 4;
            *reinterpret_cast<float4*>(&Bs[kk][nq]) =
                *reinterpret_cast<const float4*>(&B[(size_t)(k0 + kk) * M + col0 + nq]);
        }
        __syncthreads();
        #pragma unroll
        for (int kk = 0; kk < 16; kk++) {
            float4 a0 = *reinterpret_cast<const float4*>(&As[kk][tr * 8]);
            float4 a1 = *reinterpret_cast<const float4*>(&As[kk][tr * 8 + 4]);
            float4 b4 = *reinterpret_cast<const float4*>(&Bs[kk][tc * 4]);
            float a[8] = {a0.x, a0.y, a0.z, a0.w, a1.x, a1.y, a1.z, a1.w};
            float b[4] = {b4.x, b4.y, b4.z, b4.w};
            #pragma unroll
            for (int u = 0; u < 8; u++)
                #pragma unroll
                for (int v = 0; v < 4; v++)
                    acc[u][v] += a[u] * b[v];
        }
        __syncthreads();
    }
    float* C = which ? g_xr1 : g_xl1;
    #pragma unroll
    for (int u = 0; u < 8; u++) {
        int r = row0 + tr * 8 + u;
        if (r < N_NODES)
            *reinterpret_cast<float4*>(&C[(size_t)r * M + col0 + tc * 4]) =
                make_float4(acc[u][0], acc[u][1], acc[u][2], acc[u][3]);
    }
}

// ---------------- fused layer-1 GATv2 + layer-2 node transform ---------------
// one warp per (dst node, head). Registers hold xr slice + accumulators.
// Epilogue: out = acc/den; h = ELU(out + b1); partial dots with W2l/W2r
// atomically accumulated into g_hl2 / g_hr2.
__global__ __launch_bounds__(256) void k_gat1(const float* __restrict__ ea,
                                              const float* __restrict__ W1e,
                                              const float* __restrict__ att1,
                                              const float* __restrict__ b1,
                                              const float* __restrict__ W2l,
                                              const float* __restrict__ W2r) {
    __shared__ float sW[768];     // W1e (3 x 256)
    __shared__ float sA[256];     // att1
    __shared__ float sMean[3];
    int tid = threadIdx.x;
    for (int i = tid; i < 768; i += 256) sW[i] = W1e[i];
    if (tid < 256) sA[tid] = att1[tid];
    if (tid < 3) sMean[tid] = g_attr_sum[tid] * (1.0f / N_EDGES);
    __syncthreads();

    int gw = blockIdx.x * 8 + (tid >> 5);        // global warp id
    int lane = tid & 31;
    int n = gw >> 2;                             // dst node
    int h = gw & 3;                              // head
    if (n >= N_NODES) return;

    int c2 = h * 32 + lane;                      // float2 channel index
    int i = c2 * 2;                              // scalar channel index
    const float w0 = sW[i],     w1 = sW[256 + i],     w2 = sW[512 + i];
    const float w0b = sW[i + 1], w1b = sW[256 + i + 1], w2b = sW[512 + i + 1];
    const float attA = sA[i], attB = sA[i + 1];
    float2 r = reinterpret_cast<const float2*>(g_xr1)[(size_t)n * 128 + c2];

    int start = g_start[n];
    int end   = start + g_deg[n];
    float den = 0.f, ax = 0.f, ay = 0.f;
    for (int idx = start; idx < end; idx++) {
        int src = g_csr_src[idx];
        int eid = g_csr_eid[idx];
        float a0, a1, a2;
        if (eid < N_EDGES) {
            a0 = ea[eid * 3]; a1 = ea[eid * 3 + 1]; a2 = ea[eid * 3 + 2];
        } else {
            a0 = sMean[0]; a1 = sMean[1]; a2 = sMean[2];
        }
        float2 l = reinterpret_cast<const float2*>(g_xl1)[(size_t)src * 128 + c2];
        float e0 = a0 * w0  + a1 * w1  + a2 * w2;
        float e1 = a0 * w0b + a1 * w1b + a2 * w2b;
        float m0 = l.x + r.x + e0; m0 = m0 > 0.f ? m0 : NEG_SLOPE * m0;
        float m1 = l.y + r.y + e1; m1 = m1 > 0.f ? m1 : NEG_SLOPE * m1;
        float p = warp_sum_all(m0 * attA + m1 * attB);
        float ex = __expf(p);
        den += ex;
        ax += ex * l.x;
        ay += ex * l.y;
    }
    float inv = 1.0f / den;
    // layer-2 node transform fused: h = ELU(out + b1); partial dot with W2l/W2r
    float o0 = ax * inv + b1[i];
    float o1 = ay * inv + b1[i + 1];
    o0 = o0 > 0.f ? o0 : (__expf(o0) - 1.f);
    o1 = o1 > 0.f ? o1 : (__expf(o1) - 1.f);
    float pl = o0 * W2l[i] + o1 * W2l[i + 1];
    float pr = o0 * W2r[i] + o1 * W2r[i + 1];
    pl = warp_sum(pl);
    pr = warp_sum(pr);
    if (lane == 0) {
        atomicAdd(&g_hl2[n], pl);
        atomicAdd(&g_hr2[n], pr);
    }
}

// ---------------- fused layer-2 GATv2 + scores ----------------
// one warp per dst node; lanes stride over CSR entries.
__global__ __launch_bounds__(256) void k_gat2(const float* __restrict__ ea,
                                              const float* __restrict__ W2e,
                                              const float* __restrict__ att2,
                                              const float* __restrict__ b2,
                                              float* __restrict__ out) {
    __shared__ float sMean[3];
    __shared__ float sW[3];
    __shared__ float sAtt, sB2;
    if (threadIdx.x < 3) {
        sMean[threadIdx.x] = g_attr_sum[threadIdx.x] * (1.0f / N_EDGES);
        sW[threadIdx.x] = W2e[threadIdx.x];
    }
    if (threadIdx.x == 0) { sAtt = att2[0]; sB2 = b2[0]; }
    __syncthreads();

    int n = blockIdx.x * 8 + (threadIdx.x >> 5);
    int lane = threadIdx.x & 31;
    if (n >= N_NODES) return;
    float hr = g_hr2[n];
    int start = g_start[n];
    int end   = start + g_deg[n];
    float num = 0.f, den = 0.f;
    for (int idx = start + lane; idx < end; idx += 32) {
        int src = g_csr_src[idx];
        int eid = g_csr_eid[idx];
        float a0, a1, a2;
        if (eid < N_EDGES) {
            a0 = ea[eid * 3]; a1 = ea[eid * 3 + 1]; a2 = ea[eid * 3 + 2];
        } else {
            a0 = sMean[0]; a1 = sMean[1]; a2 = sMean[2];
        }
        float hl = g_hl2[src];
        float m = hl + hr + a0 * sW[0] + a1 * sW[1] + a2 * sW[2];
        m = m > 0.f ? m : NEG_SLOPE * m;
        float ex = __expf(sAtt * m);
        den += ex;
        num += ex * hl;
    }
    num = warp_sum(num);
    den = warp_sum(den);
    if (lane == 0) {
        float s = num / den + sB2;
        g_out2[n] = s;
        out[N_NODES + n] = s;
    }
}

// ---------------- global softmax ----------------
__global__ void k_smax() {
    float m = -3.0e38f;
    for (int n = blockIdx.x * blockDim.x + threadIdx.x; n < N_NODES;
         n += gridDim.x * blockDim.x)
        m = fmaxf(m, g_out2[n]);
    #pragma unroll
    for (int o = 16; o; o >>= 1)
        m = fmaxf(m, __shfl_down_sync(0xffffffffu, m, o));
    if ((threadIdx.x & 31) == 0) atomicMax(&g_smax, encf(m));
}

__global__ void k_ssum() {
    float mx = decf(g_smax);
    float s = 0.f;
    for (int n = blockIdx.x * blockDim.x + threadIdx.x; n < N_NODES;
         n += gridDim.x * blockDim.x)
        s += __expf(g_out2[n] - mx);
    s = warp_sum(s);
    if ((threadIdx.x & 31) == 0) atomicAdd(&g_ssum, s);
}

__global__ void k_weights(float* __restrict__ out) {
    float mx = decf(g_smax);
    float inv = 1.0f / g_ssum;
    int n = blockIdx.x * blockDim.x + threadIdx.x;
    if (n >= N_NODES) return;
    out[n] = __expf(g_out2[n] - mx) * inv;
}

// ---------------- launch ----------------
extern "C" void kernel_launch(void* const* d_in, const int* in_sizes, int n_in,
                              void* d_out, int out_size) {
    const float* x    = (const float*)d_in[0];
    const float* ea   = (const float*)d_in[1];
    const float* W1l  = (const float*)d_in[2];
    const float* W1r  = (const float*)d_in[3];
    const float* W1e  = (const float*)d_in[4];
    const float* att1 = (const float*)d_in[5];
    const float* b1   = (const float*)d_in[6];
    const float* W2l  = (const float*)d_in[7];
    const float* W2r  = (const float*)d_in[8];
    const float* W2e  = (const float*)d_in[9];
    const float* att2 = (const float*)d_in[10];
    const float* b2   = (const float*)d_in[11];
    const int*   ei   = (const int*)d_in[12];
    float* out = (float*)d_out;

    // init + attr mean
    k_zero<<<256, 256>>>();
    k_attr_mean<<<256, 256>>>(ea);

    // CSR build
    int ethr_blocks = (N_E2 + 255) / 256;
    k_count<<<ethr_blocks, 256>>>(ei);
    k_scan<<<1, 1024>>>();
    k_place<<<ethr_blocks, 256>>>(ei);

    // dense transforms (128x64 tiles)
    dim3 gg(4, (N_NODES + 127) / 128);
    k_sgemm<<<gg, 256>>>(x, W1l, 0);
    k_sgemm<<<gg, 256>>>(x, W1r, 1);

    // fused layer 1 (+ layer-2 node transform)
    int gat1_blocks = (N_NODES * HEADS + 7) / 8;
    k_gat1<<<gat1_blocks, 256>>>(ea, W1e, att1, b1, W2l, W2r);

    // fused layer 2 (+ scores)
    int gat2_blocks = (N_NODES + 7) / 8;
    k_gat2<<<gat2_blocks, 256>>>(ea, W2e, att2, b2, out);

    // global softmax
    int nthr_blocks = (N_NODES + 255) / 256;
    k_smax<<<128, 256>>>();
    k_ssum<<<128, 256>>>();
    k_weights<<<nthr_blocks, 256>>>(out);
}

// round 5
// speedup vs baseline: 1.6863x; 1.0327x over previous
#include <cuda_runtime.h>
#include <cstdint>

#define N_NODES 50000
#define N_EDGES 800000
#define N_E2    850000      // edges + self loops
#define IN_DIM  128
#define HID     64
#define HEADS   4
#define HC      256         // HEADS*HID
#define NEG_SLOPE 0.2f
#define N_SCAN_BLK 196      // ceil(50000/256)

// ---------------- scratch (device globals; no runtime alloc) ----------------
__device__ float    g_xl1[N_NODES * HC];
__device__ float    g_xr1[N_NODES * HC];
__device__ int      g_deg[N_NODES];
__device__ int      g_start[N_NODES];
__device__ int      g_cursor[N_NODES];
__device__ int      g_blksum[256];
__device__ int      g_blkoff[256];
__device__ int      g_csr_src[N_E2];
__device__ int      g_csr_eid[N_E2];
__device__ float    g_hl2[N_NODES];
__device__ float    g_hr2[N_NODES];
__device__ float    g_out2[N_NODES];
__device__ float    g_attr_sum[3];
__device__ unsigned g_smax;
__device__ float    g_ssum;

// ---------------- helpers ----------------
__device__ __forceinline__ unsigned encf(float f) {
    unsigned u = __float_as_uint(f);
    return (u & 0x80000000u) ? ~u : (u | 0x80000000u);
}
__device__ __forceinline__ float decf(unsigned u) {
    return (u & 0x80000000u) ? __uint_as_float(u & 0x7FFFFFFFu)
                             : __uint_as_float(~u);
}
__device__ __forceinline__ float warp_sum(float v) {
    #pragma unroll
    for (int o = 16; o; o >>= 1) v += __shfl_down_sync(0xffffffffu, v, o);
    return v;
}
__device__ __forceinline__ float warp_sum_all(float v) {
    #pragma unroll
    for (int o = 16; o; o >>= 1) v += __shfl_xor_sync(0xffffffffu, v, o);
    return v;
}
__device__ __forceinline__ float f2tf32(float x) {
    uint32_t u;
    asm("cvt.rna.tf32.f32 %0, %1;" : "=r"(u) : "f"(x));
    return __uint_as_float(u);
}
__device__ __forceinline__ void mma_tf32(float c[4],
                                         uint32_t a0, uint32_t a1, uint32_t a2, uint32_t a3,
                                         uint32_t b0, uint32_t b1) {
    asm volatile("mma.sync.aligned.m16n8k8.row.col.f32.tf32.tf32.f32 "
                 "{%0,%1,%2,%3}, {%4,%5,%6,%7}, {%8,%9}, {%0,%1,%2,%3};"
                 : "+f"(c[0]), "+f"(c[1]), "+f"(c[2]), "+f"(c[3])
                 : "r"(a0), "r"(a1), "r"(a2), "r"(a3), "r"(b0), "r"(b1));
}

// ---------------- init ----------------
__global__ void k_zero() {
    int tid = blockIdx.x * blockDim.x + threadIdx.x;
    int stride = gridDim.x * blockDim.x;
    for (int i = tid; i < N_NODES; i += stride) {
        g_deg[i] = 0; g_hl2[i] = 0.f; g_hr2[i] = 0.f;
    }
    if (tid == 0) {
        g_attr_sum[0] = 0.f; g_attr_sum[1] = 0.f; g_attr_sum[2] = 0.f;
        g_smax = 0u; g_ssum = 0.f;
    }
}

// mean of edge_attr columns (for self-loop fill)
__global__ void k_attr_mean(const float* __restrict__ ea) {
    float s0 = 0.f, s1 = 0.f, s2 = 0.f;
    for (int e = blockIdx.x * blockDim.x + threadIdx.x; e < N_EDGES;
         e += gridDim.x * blockDim.x) {
        s0 += ea[e * 3 + 0]; s1 += ea[e * 3 + 1]; s2 += ea[e * 3 + 2];
    }
    s0 = warp_sum(s0); s1 = warp_sum(s1); s2 = warp_sum(s2);
    if ((threadIdx.x & 31) == 0) {
        atomicAdd(&g_attr_sum[0], s0);
        atomicAdd(&g_attr_sum[1], s1);
        atomicAdd(&g_attr_sum[2], s2);
    }
}

// ---------------- CSR build ----------------
__global__ void k_count(const int* __restrict__ ei) {
    int e = blockIdx.x * blockDim.x + threadIdx.x;
    if (e >= N_E2) return;
    int dst = (e < N_EDGES) ? ei[N_EDGES + e] : e - N_EDGES;
    atomicAdd(&g_deg[dst], 1);
}

// parallel scan, stage 1: per-block (256 elems) exclusive scan + block sums
__global__ void k_scan1() {
    __shared__ int wTot[8];
    int tid = threadIdx.x, lane = tid & 31, wid = tid >> 5;
    int i = blockIdx.x * 256 + tid;
    int v = (i < N_NODES) ? g_deg[i] : 0;
    int x = v;
    #pragma unroll
    for (int o = 1; o < 32; o <<= 1) {
        int t = __shfl_up_sync(0xffffffffu, x, o);
        if (lane >= o) x += t;
    }
    if (lane == 31) wTot[wid] = x;
    __syncthreads();
    if (tid == 0) {
        int s = 0;
        #pragma unroll
        for (int j = 0; j < 8; j++) { int t = wTot[j]; wTot[j] = s; s += t; }
        g_blksum[blockIdx.x] = s;
    }
    __syncthreads();
    if (i < N_NODES) g_start[i] = x - v + wTot[wid];   // local exclusive
}

// stage 2: exclusive scan of block sums (single small block)
__global__ void k_scan2() {
    __shared__ int wTot[8];
    int tid = threadIdx.x, lane = tid & 31, wid = tid >> 5;
    int v = (tid < N_SCAN_BLK) ? g_blksum[tid] : 0;
    int x = v;
    #pragma unroll
    for (int o = 1; o < 32; o <<= 1) {
        int t = __shfl_up_sync(0xffffffffu, x, o);
        if (lane >= o) x += t;
    }
    if (lane == 31) wTot[wid] = x;
    __syncthreads();
    if (tid == 0) {
        int s = 0;
        #pragma unroll
        for (int j = 0; j < 8; j++) { int t = wTot[j]; wTot[j] = s; s += t; }
    }
    __syncthreads();
    g_blkoff[tid] = x - v + wTot[wid];
}

// stage 3: add block offsets
__global__ void k_scan3() {
    int i = blockIdx.x * blockDim.x + threadIdx.x;
    if (i >= N_NODES) return;
    int s = g_start[i] + g_blkoff[i >> 8];
    g_start[i] = s;
    g_cursor[i] = s;
}

__global__ void k_place(const int* __restrict__ ei) {
    int e = blockIdx.x * blockDim.x + threadIdx.x;
    if (e >= N_E2) return;
    int src, dst;
    if (e < N_EDGES) { src = ei[e]; dst = ei[N_EDGES + e]; }
    else             { src = dst = e - N_EDGES; }
    int slot = atomicAdd(&g_cursor[dst], 1);
    g_csr_src[slot] = src;
    g_csr_eid[slot] = e;
}

// ---------------- tf32 split-precision tensor-core GEMM ----------------
// C[N,256] = A[N,128] @ B[128,256]; C = Ah*Bh + Ah*Bl + Al*Bh (fp32-equivalent).
// Block: 256 thr = 8 warps (4m x 2n), block tile 128m x 64n, BK=16.
// Warp tile 32x32 = 2(m16) x 4(n8) mma tiles.
__global__ __launch_bounds__(256) void k_gemm_tf32(const float* __restrict__ A,
                                                   const float* __restrict__ B,
                                                   int which /*0->g_xl1, 1->g_xr1*/) {
    __shared__ float Ah[128][20], Al[128][20];   // stride 20 -> conflict-free frags
    __shared__ float Bh[16][72],  Bl[16][72];    // stride 72 -> conflict-free frags
    const int K = IN_DIM, M = HC;
    int row0 = blockIdx.y * 128, col0 = blockIdx.x * 64;
    int tid = threadIdx.x, lane = tid & 31, wid = tid >> 5;
    int wm = wid >> 1, wn = wid & 1;             // warp position in 4x2 grid
    float acc[2][4][4] = {};

    for (int k0 = 0; k0 < K; k0 += 16) {
        // A tile: 128 x 16 = 512 float4 loads
        #pragma unroll
        for (int i = tid; i < 512; i += 256) {
            int m = i >> 2, kq = (i & 3) * 4;
            int r = row0 + m;
            float4 v = (r < N_NODES)
                ? *reinterpret_cast<const float4*>(&A[(size_t)r * K + k0 + kq])
                : make_float4(0.f, 0.f, 0.f, 0.f);
            float h;
            h = f2tf32(v.x); Ah[m][kq + 0] = h; Al[m][kq + 0] = f2tf32(v.x - h);
            h = f2tf32(v.y); Ah[m][kq + 1] = h; Al[m][kq + 1] = f2tf32(v.y - h);
            h = f2tf32(v.z); Ah[m][kq + 2] = h; Al[m][kq + 2] = f2tf32(v.z - h);
            h = f2tf32(v.w); Ah[m][kq + 3] = h; Al[m][kq + 3] = f2tf32(v.w - h);
        }
        // B tile: 16 x 64 = 256 float4 loads
        {
            int kk = tid >> 4, nq = (tid & 15) * 4;
            float4 v = *reinterpret_cast<const float4*>(&B[(size_t)(k0 + kk) * M + col0 + nq]);
            float h;
            h = f2tf32(v.x); Bh[kk][nq + 0] = h; Bl[kk][nq + 0] = f2tf32(v.x - h);
            h = f2tf32(v.y); Bh[kk][nq + 1] = h; Bl[kk][nq + 1] = f2tf32(v.y - h);
            h = f2tf32(v.z); Bh[kk][nq + 2] = h; Bl[kk][nq + 2] = f2tf32(v.z - h);
            h = f2tf32(v.w); Bh[kk][nq + 3] = h; Bl[kk][nq + 3] = f2tf32(v.w - h);
        }
        __syncthreads();
        #pragma unroll
        for (int ks = 0; ks < 16; ks += 8) {
            uint32_t ah[2][4], al[2][4], bh[4][2], bl[4][2];
            int kk = ks + (lane & 3);
            #pragma unroll
            for (int mt = 0; mt < 2; mt++) {
                int r0 = wm * 32 + mt * 16 + (lane >> 2);
                ah[mt][0] = __float_as_uint(Ah[r0][kk]);
                ah[mt][1] = __float_as_uint(Ah[r0 + 8][kk]);
                ah[mt][2] = __float_as_uint(Ah[r0][kk + 4]);
                ah[mt][3] = __float_as_uint(Ah[r0 + 8][kk + 4]);
                al[mt][0] = __float_as_uint(Al[r0][kk]);
                al[mt][1] = __float_as_uint(Al[r0 + 8][kk]);
                al[mt][2] = __float_as_uint(Al[r0][kk + 4]);
                al[mt][3] = __float_as_uint(Al[r0 + 8][kk + 4]);
            }
            #pragma unroll
            for (int nt = 0; nt < 4; nt++) {
                int cc = wn * 32 + nt * 8 + (lane >> 2);
                bh[nt][0] = __float_as_uint(Bh[kk][cc]);
                bh[nt][1] = __float_as_uint(Bh[kk + 4][cc]);
                bl[nt][0] = __float_as_uint(Bl[kk][cc]);
                bl[nt][1] = __float_as_uint(Bl[kk + 4][cc]);
            }
            #pragma unroll
            for (int mt = 0; mt < 2; mt++)
                #pragma unroll
                for (int nt = 0; nt < 4; nt++) {
                    mma_tf32(acc[mt][nt], ah[mt][0], ah[mt][1], ah[mt][2], ah[mt][3],
                             bh[nt][0], bh[nt][1]);
                    mma_tf32(acc[mt][nt], ah[mt][0], ah[mt][1], ah[mt][2], ah[mt][3],
                             bl[nt][0], bl[nt][1]);
                    mma_tf32(acc[mt][nt], al[mt][0], al[mt][1], al[mt][2], al[mt][3],
                             bh[nt][0], bh[nt][1]);
                }
        }
        __syncthreads();
    }
    float* C = which ? g_xr1 : g_xl1;
    #pragma unroll
    for (int mt = 0; mt < 2; mt++) {
        int row = row0 + wm * 32 + mt * 16 + (lane >> 2);
        #pragma unroll
        for (int nt = 0; nt < 4; nt++) {
            int col = col0 + wn * 32 + nt * 8 + 2 * (lane & 3);
            if (row < N_NODES)
                *reinterpret_cast<float2*>(&C[(size_t)row * M + col]) =
                    make_float2(acc[mt][nt][0], acc[mt][nt][1]);
            if (row + 8 < N_NODES)
                *reinterpret_cast<float2*>(&C[(size_t)(row + 8) * M + col]) =
                    make_float2(acc[mt][nt][2], acc[mt][nt][3]);
        }
    }
}

// ---------------- fused layer-1 GATv2 + layer-2 node transform ---------------
// one warp per (dst node, head).
__global__ __launch_bounds__(256) void k_gat1(const float* __restrict__ ea,
                                              const float* __restrict__ W1e,
                                              const float* __restrict__ att1,
                                              const float* __restrict__ b1,
                                              const float* __restrict__ W2l,
                                              const float* __restrict__ W2r) {
    __shared__ float sW[768];     // W1e (3 x 256)
    __shared__ float sA[256];     // att1
    __shared__ float sMean[3];
    int tid = threadIdx.x;
    for (int i = tid; i < 768; i += 256) sW[i] = W1e[i];
    if (tid < 256) sA[tid] = att1[tid];
    if (tid < 3) sMean[tid] = g_attr_sum[tid] * (1.0f / N_EDGES);
    __syncthreads();

    int gw = blockIdx.x * 8 + (tid >> 5);
    int lane = tid & 31;
    int n = gw >> 2;
    int h = gw & 3;
    if (n >= N_NODES) return;

    int c2 = h * 32 + lane;
    int i = c2 * 2;
    const float w0 = sW[i],     w1 = sW[256 + i],     w2 = sW[512 + i];
    const float w0b = sW[i + 1], w1b = sW[256 + i + 1], w2b = sW[512 + i + 1];
    const float attA = sA[i], attB = sA[i + 1];
    float2 r = reinterpret_cast<const float2*>(g_xr1)[(size_t)n * 128 + c2];

    int start = g_start[n];
    int end   = start + g_deg[n];
    float den = 0.f, ax = 0.f, ay = 0.f;
    for (int idx = start; idx < end; idx++) {
        int src = g_csr_src[idx];
        int eid = g_csr_eid[idx];
        float a0, a1, a2;
        if (eid < N_EDGES) {
            a0 = ea[eid * 3]; a1 = ea[eid * 3 + 1]; a2 = ea[eid * 3 + 2];
        } else {
            a0 = sMean[0]; a1 = sMean[1]; a2 = sMean[2];
        }
        float2 l = reinterpret_cast<const float2*>(g_xl1)[(size_t)src * 128 + c2];
        float e0 = a0 * w0  + a1 * w1  + a2 * w2;
        float e1 = a0 * w0b + a1 * w1b + a2 * w2b;
        float m0 = l.x + r.x + e0; m0 = m0 > 0.f ? m0 : NEG_SLOPE * m0;
        float m1 = l.y + r.y + e1; m1 = m1 > 0.f ? m1 : NEG_SLOPE * m1;
        float p = warp_sum_all(m0 * attA + m1 * attB);
        float ex = __expf(p);
        den += ex;
        ax += ex * l.x;
        ay += ex * l.y;
    }
    float inv = 1.0f / den;
    float o0 = ax * inv + b1[i];
    float o1 = ay * inv + b1[i + 1];
    o0 = o0 > 0.f ? o0 : (__expf(o0) - 1.f);
    o1 = o1 > 0.f ? o1 : (__expf(o1) - 1.f);
    float pl = o0 * W2l[i] + o1 * W2l[i + 1];
    float pr = o0 * W2r[i] + o1 * W2r[i + 1];
    pl = warp_sum(pl);
    pr = warp_sum(pr);
    if (lane == 0) {
        atomicAdd(&g_hl2[n], pl);
        atomicAdd(&g_hr2[n], pr);
    }
}

// ---------------- fused layer-2 GATv2 + scores ----------------
__global__ __launch_bounds__(256) void k_gat2(const float* __restrict__ ea,
                                              const float* __restrict__ W2e,
                                              const float* __restrict__ att2,
                                              const float* __restrict__ b2,
                                              float* __restrict__ out) {
    __shared__ float sMean[3];
    __shared__ float sW[3];
    __shared__ float sAtt, sB2;
    if (threadIdx.x < 3) {
        sMean[threadIdx.x] = g_attr_sum[threadIdx.x] * (1.0f / N_EDGES);
        sW[threadIdx.x] = W2e[threadIdx.x];
    }
    if (threadIdx.x == 0) { sAtt = att2[0]; sB2 = b2[0]; }
    __syncthreads();

    int n = blockIdx.x * 8 + (threadIdx.x >> 5);
    int lane = threadIdx.x & 31;
    if (n >= N_NODES) return;
    float hr = g_hr2[n];
    int start = g_start[n];
    int end   = start + g_deg[n];
    float num = 0.f, den = 0.f;
    for (int idx = start + lane; idx < end; idx += 32) {
        int src = g_csr_src[idx];
        int eid = g_csr_eid[idx];
        float a0, a1, a2;
        if (eid < N_EDGES) {
            a0 = ea[eid * 3]; a1 = ea[eid * 3 + 1]; a2 = ea[eid * 3 + 2];
        } else {
            a0 = sMean[0]; a1 = sMean[1]; a2 = sMean[2];
        }
        float hl = g_hl2[src];
        float m = hl + hr + a0 * sW[0] + a1 * sW[1] + a2 * sW[2];
        m = m > 0.f ? m : NEG_SLOPE * m;
        float ex = __expf(sAtt * m);
        den += ex;
        num += ex * hl;
    }
    num = warp_sum(num);
    den = warp_sum(den);
    if (lane == 0) {
        float s = num / den + sB2;
        g_out2[n] = s;
        out[N_NODES + n] = s;
    }
}

// ---------------- global softmax ----------------
__global__ void k_smax() {
    float m = -3.0e38f;
    for (int n = blockIdx.x * blockDim.x + threadIdx.x; n < N_NODES;
         n += gridDim.x * blockDim.x)
        m = fmaxf(m, g_out2[n]);
    #pragma unroll
    for (int o = 16; o; o >>= 1)
        m = fmaxf(m, __shfl_down_sync(0xffffffffu, m, o));
    if ((threadIdx.x & 31) == 0) atomicMax(&g_smax, encf(m));
}

__global__ void k_ssum() {
    float mx = decf(g_smax);
    float s = 0.f;
    for (int n = blockIdx.x * blockDim.x + threadIdx.x; n < N_NODES;
         n += gridDim.x * blockDim.x)
        s += __expf(g_out2[n] - mx);
    s = warp_sum(s);
    if ((threadIdx.x & 31) == 0) atomicAdd(&g_ssum, s);
}

__global__ void k_weights(float* __restrict__ out) {
    float mx = decf(g_smax);
    float inv = 1.0f / g_ssum;
    int n = blockIdx.x * blockDim.x + threadIdx.x;
    if (n >= N_NODES) return;
    out[n] = __expf(g_out2[n] - mx) * inv;
}

// ---------------- launch ----------------
extern "C" void kernel_launch(void* const* d_in, const int* in_sizes, int n_in,
                              void* d_out, int out_size) {
    const float* x    = (const float*)d_in[0];
    const float* ea   = (const float*)d_in[1];
    const float* W1l  = (const float*)d_in[2];
    const float* W1r  = (const float*)d_in[3];
    const float* W1e  = (const float*)d_in[4];
    const float* att1 = (const float*)d_in[5];
    const float* b1   = (const float*)d_in[6];
    const float* W2l  = (const float*)d_in[7];
    const float* W2r  = (const float*)d_in[8];
    const float* W2e  = (const float*)d_in[9];
    const float* att2 = (const float*)d_in[10];
    const float* b2   = (const float*)d_in[11];
    const int*   ei   = (const int*)d_in[12];
    float* out = (float*)d_out;

    // init + attr mean
    k_zero<<<256, 256>>>();
    k_attr_mean<<<256, 256>>>(ea);

    // CSR build (parallel scan)
    int ethr_blocks = (N_E2 + 255) / 256;
    k_count<<<ethr_blocks, 256>>>(ei);
    k_scan1<<<N_SCAN_BLK, 256>>>();
    k_scan2<<<1, 256>>>();
    k_scan3<<<(N_NODES + 255) / 256, 256>>>();
    k_place<<<ethr_blocks, 256>>>(ei);

    // dense transforms (tf32 split-precision tensor cores)
    dim3 gg(4, (N_NODES + 127) / 128);
    k_gemm_tf32<<<gg, 256>>>(x, W1l, 0);
    k_gemm_tf32<<<gg, 256>>>(x, W1r, 1);

    // fused layer 1 (+ layer-2 node transform)
    int gat1_blocks = (N_NODES * HEADS + 7) / 8;
    k_gat1<<<gat1_blocks, 256>>>(ea, W1e, att1, b1, W2l, W2r);

    // fused layer 2 (+ scores)
    int gat2_blocks = (N_NODES + 7) / 8;
    k_gat2<<<gat2_blocks, 256>>>(ea, W2e, att2, b2, out);

    // global softmax
    int nthr_blocks = (N_NODES + 255) / 256;
    k_smax<<<128, 256>>>();
    k_ssum<<<128, 256>>>();
    k_weights<<<nthr_blocks, 256>>>(out);
}